// round 2
// baseline (speedup 1.0000x reference)
#include <cuda_runtime.h>
#include <math.h>

#define BB 8
#define TT 64
#define NN 256
#define HH 256
#define DI 6
#define DO 9
#define G3 (3*HH)   // 768
#define NBLK 128

typedef unsigned long long u64;

// ---------------- scratch (device globals; no runtime allocation) ----------------
__device__ __align__(16) float g_gx[(size_t)BB*TT*NN*G3];     // gx for current layer, all t
__device__ __align__(16) float g_hseq[(size_t)BB*TT*NN*HH];   // hidden sequence of current layer
__device__ __align__(16) float g_Axseq[(size_t)BB*TT*NN*HH];  // A ⊛ hseq (layer-1 prep)
__device__ __align__(16) float g_h [BB*NN*HH];
__device__ __align__(16) float g_Ah[BB*NN*HH];
__device__ __align__(16) float g_Au[BB*NN*HH];
__device__ __align__(16) float g_pzr[(size_t)2*BB*NN*512];    // zr GEMM K-split partials
__device__ __align__(16) float g_pc [(size_t)4*BB*NN*256];    // c GEMM K-split partials
__device__ int   g_cnt[NN];
__device__ int   g_col[NN*NN];
__device__ float g_val[NN*NN];

// grid barrier state
__device__ unsigned g_barcnt;
__device__ volatile unsigned g_bargen;

// ---------------- f32x2 helpers ----------------
__device__ __forceinline__ u64 pack2(float x, float y){
    u64 r; asm("mov.b64 %0, {%1, %2};" : "=l"(r) : "f"(x), "f"(y)); return r;
}
__device__ __forceinline__ u64 dup2(float x){ return pack2(x, x); }
__device__ __forceinline__ void ffma2(u64& d, u64 a, u64 b){
    asm("fma.rn.f32x2 %0, %1, %2, %0;" : "+l"(d) : "l"(a), "l"(b));
}
__device__ __forceinline__ float2 unpack2(u64 v){
    float2 f; asm("mov.b64 {%0, %1}, %2;" : "=f"(f.x), "=f"(f.y) : "l"(v)); return f;
}
__device__ __forceinline__ float sigmoidf_(float x){ return 1.0f / (1.0f + __expf(-x)); }

// ---------------- grid barrier (all NBLK blocks resident) ----------------
__device__ __forceinline__ void gridbar(unsigned* gen){
    __syncthreads();
    if (threadIdx.x == 0){
        __threadfence();
        unsigned target = *gen + 1;
        if (atomicAdd(&g_barcnt, 1u) == NBLK - 1){
            g_barcnt = 0;
            __threadfence();
            g_bargen = target;
        } else {
            while (g_bargen != target) __nanosleep(32);
        }
        *gen = target;
    }
    __syncthreads();
}

// ---------------- CSR build from dense adjacency (zeros are exact) ----------------
__global__ void build_csr(const float* __restrict__ adj){
    int n = threadIdx.x;
    int c = 0;
    for (int m = 0; m < NN; m++){
        float v = adj[n*NN + m];
        if (v != 0.0f){ g_col[n*NN + c] = m; g_val[n*NN + c] = v; c++; }
    }
    g_cnt[n] = c;
}

// ---------------- layer-0 gx: per (b,t), gx = (A ⊛ (x*mask)) @ Wx0 + b0 ----------------
__global__ void prep_gx0(const float* __restrict__ x2d, const float* __restrict__ mask,
                         const float* __restrict__ Wx0, const float* __restrict__ b0){
    __shared__ float xm[NN*DI];
    __shared__ float ax[NN*DI];
    __shared__ float Ws[DI*G3];
    int bt = blockIdx.x;
    int tid = threadIdx.x;

    for (int i = tid; i < NN*DI; i += 256){
        int n = i / DI;
        xm[i] = x2d[(size_t)bt*NN*DI + i] * mask[(size_t)bt*NN + n];
    }
    for (int i = tid; i < DI*G3; i += 256) Ws[i] = Wx0[i];
    __syncthreads();

    {   // sparse conv: one node per thread
        int n = tid;
        float a0=0,a1=0,a2=0,a3=0,a4=0,a5=0;
        int cn = g_cnt[n];
        for (int e = 0; e < cn; e++){
            int m = g_col[n*NN + e];
            float w = g_val[n*NN + e];
            const float* xr = xm + m*DI;
            a0 += w*xr[0]; a1 += w*xr[1]; a2 += w*xr[2];
            a3 += w*xr[3]; a4 += w*xr[4]; a5 += w*xr[5];
        }
        float* ar = ax + n*DI;
        ar[0]=a0; ar[1]=a1; ar[2]=a2; ar[3]=a3; ar[4]=a4; ar[5]=a5;
    }
    __syncthreads();

    for (int jj = 0; jj < 3; jj++){
        int j = tid + (jj << 8);
        float w0=Ws[j], w1=Ws[G3+j], w2=Ws[2*G3+j], w3=Ws[3*G3+j], w4=Ws[4*G3+j], w5=Ws[5*G3+j];
        float bj = b0[j];
        float* gout = g_gx + (size_t)bt*NN*G3 + j;
        for (int n = 0; n < NN; n++){
            const float* axr = ax + n*DI;
            float s = bj + axr[0]*w0 + axr[1]*w1 + axr[2]*w2
                         + axr[3]*w3 + axr[4]*w4 + axr[5]*w5;
            gout[(size_t)n*G3] = s;
        }
    }
}

// ---------------- 128x128 f32x2 GEMM tile (8x8 micro, K-chunked by 16) ----------------
// Ap: A pre-offset to (r0, k0), row stride lda. Bp: B pre-offset to (k0, j0), stride ldb.
// Cp: C pre-offset to (r0, j0), stride ldc. bias (len>=128 at j0) or null. KL: K length.
__device__ __forceinline__ void gemm128(const float* __restrict__ Ap, int lda, int acg,
                                        const float* __restrict__ Bp, int ldb,
                                        float* __restrict__ Cp, int ldc,
                                        const float* __restrict__ bias, int KL,
                                        float* sA, float* sB)
{
    int tid = threadIdx.x;
    int ty = tid >> 4, tx = tid & 15;
    int lrow = tid >> 1;
    int lk = (tid & 1) << 3;
    int bpk = tid >> 4;
    int bc = (tid & 15) << 3;
    u64 acc[4][8];
    #pragma unroll
    for (int i = 0; i < 4; i++)
        #pragma unroll
        for (int j = 0; j < 8; j++) acc[i][j] = 0ull;

    for (int kc = 0; kc < KL; kc += 16){
        const float4* ag = (const float4*)(Ap + (size_t)lrow*lda + kc + lk);
        float4 a0, a1;
        if (acg){ a0 = __ldcg(ag); a1 = __ldcg(ag + 1); }
        else    { a0 = ag[0];      a1 = ag[1]; }
        sA[(lk+0)*132 + lrow] = a0.x; sA[(lk+1)*132 + lrow] = a0.y;
        sA[(lk+2)*132 + lrow] = a0.z; sA[(lk+3)*132 + lrow] = a0.w;
        sA[(lk+4)*132 + lrow] = a1.x; sA[(lk+5)*132 + lrow] = a1.y;
        sA[(lk+6)*132 + lrow] = a1.z; sA[(lk+7)*132 + lrow] = a1.w;
        const float4* bg = (const float4*)(Bp + (size_t)(kc + bpk)*ldb + bc);
        *(float4*)(sB + bpk*132 + bc)     = bg[0];
        *(float4*)(sB + bpk*132 + bc + 4) = bg[1];
        __syncthreads();
        #pragma unroll
        for (int p = 0; p < 16; p++){
            const float4* av = (const float4*)(sA + p*132 + ty*8);
            float4 A0 = av[0], A1 = av[1];
            u64 ar[4];
            ar[0] = pack2(A0.x, A0.y); ar[1] = pack2(A0.z, A0.w);
            ar[2] = pack2(A1.x, A1.y); ar[3] = pack2(A1.z, A1.w);
            const float4* bv = (const float4*)(sB + p*132 + tx*8);
            float4 B0 = bv[0], B1 = bv[1];
            u64 bd[8];
            bd[0]=dup2(B0.x); bd[1]=dup2(B0.y); bd[2]=dup2(B0.z); bd[3]=dup2(B0.w);
            bd[4]=dup2(B1.x); bd[5]=dup2(B1.y); bd[6]=dup2(B1.z); bd[7]=dup2(B1.w);
            #pragma unroll
            for (int i = 0; i < 4; i++)
                #pragma unroll
                for (int j = 0; j < 8; j++) ffma2(acc[i][j], ar[i], bd[j]);
        }
        __syncthreads();
    }

    float bb[8];
    if (bias){
        #pragma unroll
        for (int j = 0; j < 8; j++) bb[j] = bias[tx*8 + j];
    } else {
        #pragma unroll
        for (int j = 0; j < 8; j++) bb[j] = 0.0f;
    }
    #pragma unroll
    for (int ri = 0; ri < 4; ri++){
        float2 c[8];
        #pragma unroll
        for (int j = 0; j < 8; j++){ c[j] = unpack2(acc[ri][j]); c[j].x += bb[j]; c[j].y += bb[j]; }
        float* row0 = Cp + (size_t)(ty*8 + ri*2)*ldc + tx*8;
        float* row1 = row0 + ldc;
        float4 v0 = make_float4(c[0].x, c[1].x, c[2].x, c[3].x);
        float4 v1 = make_float4(c[4].x, c[5].x, c[6].x, c[7].x);
        float4 w0 = make_float4(c[0].y, c[1].y, c[2].y, c[3].y);
        float4 w1 = make_float4(c[4].y, c[5].y, c[6].y, c[7].y);
        *(float4*)row0 = v0; *(float4*)(row0 + 4) = v1;
        *(float4*)row1 = w0; *(float4*)(row1 + 4) = w1;
    }
}

// ---------------- smem spconv: out[n][0..15] = sum_e w * su[m][0..15] ----------------
__device__ __forceinline__ void spconv16(const float* su, float* dstbase, int q, int j2b){
    int n = threadIdx.x;
    float acc[16];
    #pragma unroll
    for (int k = 0; k < 16; k++) acc[k] = 0.0f;
    int cn = g_cnt[n];
    const int*   cp = g_col + n*NN;
    const float* vp = g_val + n*NN;
    for (int e = 0; e < cn; e++){
        int m = cp[e]; float w = vp[e];
        const float* sm = su + m*17;
        #pragma unroll
        for (int k = 0; k < 16; k++) acc[k] += w * sm[k];
    }
    float* dst = dstbase + ((size_t)(q<<8) + n)*HH + j2b;
    #pragma unroll
    for (int k = 0; k < 16; k++) dst[k] = acc[k];
}

// ---------------- persistent per-layer recurrence kernel ----------------
__global__ void __launch_bounds__(256, 1) gcgru_layer(const float* __restrict__ Wh){
    __shared__ __align__(16) float SBUF[4608];
    float* sA = SBUF;
    float* sB = SBUF + 2112;
    int tid = threadIdx.x;
    int bid = blockIdx.x;
    unsigned gen = g_bargen;

    // init: zero h and Ah
    {
        float4 z4 = make_float4(0,0,0,0);
        float4* h4 = (float4*)g_h;
        float4* a4 = (float4*)g_Ah;
        for (int i = bid*256 + tid; i < BB*NN*HH/4; i += NBLK*256){ h4[i] = z4; a4[i] = z4; }
    }
    gridbar(&gen);

    int q   = bid >> 4;        // batch for epi/spconv phases
    int j2b = (bid & 15) << 4; // 16-col slice
    int grp = tid >> 4, ln = tid & 15;

    for (int t = 0; t < TT; t++){
        // ---- P1: zr partial GEMM (64 tiles x K-split 2) ----
        {
            int tile = bid & 63, ks = bid >> 6;
            int r0 = (tile & 15) << 7;
            int j0 = (tile >> 4) << 7;
            int k0 = ks << 7;
            gemm128(g_Ah + (size_t)r0*HH + k0, HH, 1,
                    Wh + (size_t)k0*G3 + j0, G3,
                    g_pzr + (size_t)ks*(BB*NN*512) + (size_t)r0*512 + j0, 512,
                    (const float*)0, 128, sA, sB);
        }
        gridbar(&gen);
        // ---- P2: r-gate epilogue + u=r*h + spconv -> Au ----
        {
            float* su = SBUF;
            #pragma unroll 4
            for (int mb = 0; mb < 16; mb++){
                int m = (mb << 4) + grp;
                int row = (q << 8) + m;
                int j2 = j2b + ln;
                size_t rowt = (size_t)((q << 6) + t)*256 + m;
                float v = __ldcg(&g_pzr[(size_t)row*512 + 256 + j2])
                        + __ldcg(&g_pzr[(size_t)(BB*NN*512) + (size_t)row*512 + 256 + j2])
                        + g_gx[rowt*G3 + 256 + j2];
                float r = sigmoidf_(v);
                su[m*17 + ln] = r * __ldcg(&g_h[(size_t)row*HH + j2]);
            }
            __syncthreads();
            spconv16(su, g_Au, q, j2b);
        }
        gridbar(&gen);
        // ---- P3: c partial GEMM (32 tiles x K-split 4) ----
        {
            int tile = bid & 31, ks = bid >> 5;
            int r0 = (tile & 15) << 7;
            int j0 = (tile >> 4) << 7;
            int k0 = ks << 6;
            gemm128(g_Au + (size_t)r0*HH + k0, HH, 1,
                    Wh + (size_t)k0*G3 + 512 + j0, G3,
                    g_pc + (size_t)ks*(BB*NN*256) + (size_t)r0*256 + j0, 256,
                    (const float*)0, 64, sA, sB);
        }
        gridbar(&gen);
        // ---- P4: z & c epilogue, h update, hseq write, spconv -> Ah ----
        {
            float* sh = SBUF;
            #pragma unroll 4
            for (int mb = 0; mb < 16; mb++){
                int m = (mb << 4) + grp;
                int row = (q << 8) + m;
                int j2 = j2b + ln;
                size_t rowt = (size_t)((q << 6) + t)*256 + m;
                float cv = __ldcg(&g_pc[(size_t)row*256 + j2])
                         + __ldcg(&g_pc[(size_t)1*(BB*NN*256) + (size_t)row*256 + j2])
                         + __ldcg(&g_pc[(size_t)2*(BB*NN*256) + (size_t)row*256 + j2])
                         + __ldcg(&g_pc[(size_t)3*(BB*NN*256) + (size_t)row*256 + j2])
                         + g_gx[rowt*G3 + 512 + j2];
                float zv = __ldcg(&g_pzr[(size_t)row*512 + j2])
                         + __ldcg(&g_pzr[(size_t)(BB*NN*512) + (size_t)row*512 + j2])
                         + g_gx[rowt*G3 + j2];
                zv = sigmoidf_(zv);
                float cc = tanhf(cv);
                float hold = __ldcg(&g_h[(size_t)row*HH + j2]);
                float hn = zv*hold + (1.0f - zv)*cc;
                g_h[(size_t)row*HH + j2] = hn;
                g_hseq[rowt*HH + j2] = hn;
                sh[m*17 + ln] = hn;
            }
            __syncthreads();
            spconv16(sh, g_Ah, q, j2b);
        }
        gridbar(&gen);
    }
}

// ---------------- sequence sparse conv (layer-1 prep): g_Axseq = A ⊛ g_hseq ----------------
__global__ void spconv_seq(){
    __shared__ float Xs[NN*32];
    int kh = blockIdx.x;       // 0..7
    int q  = blockIdx.y;       // 0..511
    int tid = threadIdx.x;
    const float4* X4 = (const float4*)g_hseq;
    float4* Xs4 = (float4*)Xs;
    for (int i = tid; i < NN*8; i += 256){
        int m = i >> 3, c4 = i & 7;
        Xs4[i] = X4[((size_t)q*NN + m)*64 + kh*8 + c4];
    }
    __syncthreads();
    int k  = tid & 31;
    int ng = tid >> 5;         // 0..7
    for (int nb = 0; nb < NN; nb += 8){
        int n = nb + ng;
        int cn = g_cnt[n];
        const int*   cp = g_col + n*NN;
        const float* vp = g_val + n*NN;
        float a0 = 0.0f, a1 = 0.0f;
        int e = 0;
        for (; e + 2 <= cn; e += 2){
            a0 += vp[e]   * Xs[(cp[e]   << 5) + k];
            a1 += vp[e+1] * Xs[(cp[e+1] << 5) + k];
        }
        if (e < cn) a0 += vp[e] * Xs[(cp[e] << 5) + k];
        g_Axseq[((size_t)q*NN + n)*HH + (kh << 5) + k] = a0 + a1;
    }
}

// layer-1 gx: g_gx = g_Axseq @ Wx1 + b1   ([131072,256] x [256,768])
__global__ void __launch_bounds__(256, 1) gemm_gx1(const float* __restrict__ Wx1,
                                                   const float* __restrict__ b1){
    __shared__ __align__(16) float sA[2112];
    __shared__ __align__(16) float sB[2112];
    int r0 = blockIdx.y << 7;
    int j0 = blockIdx.x << 7;
    gemm128(g_Axseq + (size_t)r0*HH, HH, 0,
            Wx1 + j0, G3,
            g_gx + (size_t)r0*G3 + j0, G3,
            b1 + j0, 256, sA, sB);
}

// output head: out = g_hseq @ Wout + bout   ([131072,256] x [256,9])
__global__ void out_head(const float* __restrict__ Wout, const float* __restrict__ bout,
                         float* __restrict__ out){
    __shared__ float sh[32*257];
    __shared__ float Ws[HH*DO];
    __shared__ float bs[DO];
    int r0 = blockIdx.x * 32;
    int tid = threadIdx.x;
    for (int i = tid; i < HH*DO; i += 256) Ws[i] = Wout[i];
    if (tid < DO) bs[tid] = bout[tid];
    const float4* H4 = (const float4*)g_hseq;
    for (int i = tid; i < 32*64; i += 256){
        int rr = i >> 6, c4 = i & 63;
        float4 v = H4[((size_t)(r0 + rr))*64 + c4];
        float* dst = &sh[rr*257 + c4*4];
        dst[0]=v.x; dst[1]=v.y; dst[2]=v.z; dst[3]=v.w;
    }
    __syncthreads();
    for (int oi = tid; oi < 32*DO; oi += 256){
        int rr = oi / DO, c = oi % DO;
        float a0 = bs[c], a1 = 0.0f;
        const float* sr = &sh[rr*257];
        for (int k = 0; k < HH; k += 2){
            a0 += sr[k]   * Ws[k*DO + c];
            a1 += sr[k+1] * Ws[(k+1)*DO + c];
        }
        out[(size_t)(r0 + rr)*DO + c] = a0 + a1;
    }
}

// ---------------- launch ----------------
extern "C" void kernel_launch(void* const* d_in, const int* in_sizes, int n_in,
                              void* d_out, int out_size) {
    const float* x2d  = (const float*)d_in[0];
    const float* mask = (const float*)d_in[1];
    const float* adj  = (const float*)d_in[2];
    const float* Wx0  = (const float*)d_in[3];
    const float* Wh0  = (const float*)d_in[4];
    const float* b0   = (const float*)d_in[5];
    const float* Wx1  = (const float*)d_in[6];
    const float* Wh1  = (const float*)d_in[7];
    const float* b1   = (const float*)d_in[8];
    const float* Wout = (const float*)d_in[9];
    const float* bout = (const float*)d_in[10];
    float* out = (float*)d_out;

    build_csr<<<1, 256>>>(adj);
    prep_gx0<<<BB*TT, 256>>>(x2d, mask, Wx0, b0);

    // ---- layer 0 recurrence (one persistent kernel) ----
    gcgru_layer<<<NBLK, 256>>>(Wh0);

    // ---- layer 1 gx precompute (parallel over all t) ----
    spconv_seq<<<dim3(8, BB*TT), 256>>>();
    gemm_gx1<<<dim3(6, (BB*TT*NN)/128), 256>>>(Wx1, b1);

    // ---- layer 1 recurrence ----
    gcgru_layer<<<NBLK, 256>>>(Wh1);

    // ---- output head ----
    out_head<<<(BB*TT*NN)/32, 256>>>(Wout, bout, out);
}